// round 16
// baseline (speedup 1.0000x reference)
#include <cuda_runtime.h>
#include <cuda_bf16.h>

// BodyKinematics tree FK. B=4096, N=256, E=255.
// Round 16: R15 (PDL pack + lean fk) with two register-neutral trims:
//  - la staged through the upper region of S via 3 coalesced LDG rounds
//    (kills the last uncoalesced global loads),
//  - exp(2x) folded to one ex2.approx(x * 2*log2(e)).

#define NN 256
#define EE 255
#define PI_F 3.14159265358979f
#define TWO_LOG2E 2.88539008177793f   // 2 * log2(e)
#define LA_OFF 1024                   // float offset of la staging inside S

__device__ float4 g_tip[3 * EE];   // [row][edge] planes, lane-coalesced reads

__global__ void pack_kernel(const float* __restrict__ tip) {
    const int j = blockIdx.x * blockDim.x + threadIdx.x;   // float4 index in (E,4,4)
    if (j < EE * 4) {
        const int e = j >> 2, row = j & 3;
        const float4 v = ((const float4*)tip)[j];
        if (row < 3) g_tip[row * EE + e] = v;
    }
    cudaTriggerProgrammaticLaunchCompletion();
}

__device__ __forceinline__ float ftanh(float x) {
    float ax = fabsf(x);
    float t;
    asm("ex2.approx.f32 %0, %1;" : "=f"(t) : "f"(ax * TWO_LOG2E));  // exp(2*ax)
    float r = __fdividef(t - 1.0f, t + 1.0f);
    r = ax > 40.0f ? 1.0f : r;
    return copysignf(r, x);
}

// world_row = P.x*L0 + P.y*L1 + P.z*L2 (+ P.w in translation slot)
__device__ __forceinline__ float4 aff(float4 P, float4 L0, float4 L1, float4 L2) {
    float4 w;
    w.x = fmaf(P.x, L0.x, fmaf(P.y, L1.x, P.z * L2.x));
    w.y = fmaf(P.x, L0.y, fmaf(P.y, L1.y, P.z * L2.y));
    w.z = fmaf(P.x, L0.z, fmaf(P.y, L1.z, P.z * L2.z));
    w.w = fmaf(P.x, L0.w, fmaf(P.y, L1.w, fmaf(P.z, L2.w, P.w)));
    return w;
}

__global__ __launch_bounds__(256) void fk_kernel(
    const float* __restrict__ la,    // (B, 3E)
    float* __restrict__ out)         // (B, N, 4, 4)
{
    // FIRST: wait for pack_kernel's g_tip writes (zero liveness here).
    cudaGridDependencySynchronize();

    // S: worlds as S[node*3 + row] (stride-3 float4, conflict-free). Its
    // float-view region [LA_OFF, LA_OFF+765) stages la first; those cells
    // (float4 256..447) are only overwritten by the tree >=2 barriers after
    // all angle reads. Root seed (float4 0..2) is disjoint from the staging.
    __shared__ float4 S[NN * 3];
    float* Sf = (float*)S;

    const int b = blockIdx.x;
    const int t = threadIdx.x;

    // ---- Stage la: 3 coalesced LDG.32 rounds into Sf[LA_OFF..] ----
    const float* lab = la + (size_t)b * (3 * EE);
    #pragma unroll
    for (int k = 0; k < 3; ++k) {
        const int j = k * NN + t;
        if (j < 3 * EE) Sf[LA_OFF + j] = __ldg(lab + j);
    }
    __syncthreads();

    float4 L0, L1, L2;   // local affine rows for node t+1 (edge t)

    if (t < EE) {
        const float tha = PI_F * ftanh(Sf[LA_OFF + 3 * t]);
        const float thb = PI_F * ftanh(Sf[LA_OFF + 3 * t + 1]);
        const float thc = PI_F * ftanh(Sf[LA_OFF + 3 * t + 2]);

        float sa, ca, sb, cb, sc, cc;
        __sincosf(tha, &sa, &ca);
        __sincosf(thb, &sb, &cb);
        __sincosf(thc, &sc, &cc);

        // M = Rx(a) * Ry(b) * Rz(c)
        float M[9];
        M[0] = cb * cc;
        M[1] = -cb * sc;
        M[2] = sb;
        M[3] = fmaf(sa * sb, cc, ca * sc);
        M[4] = fmaf(-sa * sb, sc, ca * cc);
        M[5] = -sa * cb;
        M[6] = fmaf(-ca * sb, cc, sa * sc);
        M[7] = fmaf(ca * sb, sc, sa * cc);
        M[8] = ca * cb;

        const float4 T0 = g_tip[t];
        const float4 T1 = g_tip[EE + t];
        const float4 T2 = g_tip[2 * EE + t];
        #define MT(r, D)                                                        \
            D.x = fmaf(M[3*r], T0.x, fmaf(M[3*r+1], T1.x, M[3*r+2] * T2.x));    \
            D.y = fmaf(M[3*r], T0.y, fmaf(M[3*r+1], T1.y, M[3*r+2] * T2.y));    \
            D.z = fmaf(M[3*r], T0.z, fmaf(M[3*r+1], T1.z, M[3*r+2] * T2.z));    \
            D.w = fmaf(M[3*r], T0.w, fmaf(M[3*r+1], T1.w, M[3*r+2] * T2.w));
        MT(0, L0) MT(1, L1) MT(2, L2)
        #undef MT
    } else {
        // Root: identity world (floats 0..11, disjoint from la staging).
        S[0] = make_float4(1.f, 0.f, 0.f, 0.f);
        S[1] = make_float4(0.f, 1.f, 0.f, 0.f);
        S[2] = make_float4(0.f, 0.f, 1.f, 0.f);
    }
    __syncthreads();

    // Level-parallel tree on node n = t+1: levels lo = 1,3,7,15,31,63,127,255.
    const int n = t + 1;   // thread 255 -> n=256, never active below
    #pragma unroll
    for (int lo = 1; lo < NN; lo = 2 * lo + 1) {
        const int hi = (2 * lo + 1 < NN) ? (2 * lo + 1) : NN;
        if (n >= lo && n < hi) {
            const int p = (n - 1) >> 1;
            const float4 P0 = S[3 * p], P1 = S[3 * p + 1], P2 = S[3 * p + 2];
            S[3 * n]     = aff(P0, L0, L1, L2);
            S[3 * n + 1] = aff(P1, L0, L1, L2);
            S[3 * n + 2] = aff(P2, L0, L1, L2);
        }
        __syncthreads();
    }

    // Coalesced output: CTA writes its 16KB block in 4 contiguous rounds.
    float4* o = (float4*)(out + (size_t)b * NN * 16);
    const float4 r3 = make_float4(0.f, 0.f, 0.f, 1.f);
    #pragma unroll
    for (int k = 0; k < 4; ++k) {
        const int j = k * NN + t;
        const int node = j >> 2, row = j & 3;
        o[j] = (row < 3) ? S[3 * node + row] : r3;
    }
}

extern "C" void kernel_launch(void* const* d_in, const int* in_sizes, int n_in,
                              void* d_out, int out_size) {
    const float* la  = (const float*)d_in[0];
    const float* tip = (const float*)d_in[1];
    float* out = (float*)d_out;

    const int B = in_sizes[0] / (3 * EE);

    pack_kernel<<<4, 256>>>(tip);

    cudaLaunchConfig_t cfg = {};
    cfg.gridDim = dim3((unsigned)B);
    cfg.blockDim = dim3(NN);
    cfg.dynamicSmemBytes = 0;
    cfg.stream = 0;
    cudaLaunchAttribute attr[1];
    attr[0].id = cudaLaunchAttributeProgrammaticStreamSerialization;
    attr[0].val.programmaticStreamSerializationAllowed = 1;
    cfg.attrs = attr;
    cfg.numAttrs = 1;
    cudaLaunchKernelEx(&cfg, fk_kernel, la, out);
}

// round 17
// speedup vs baseline: 1.0882x; 1.0882x over previous
#include <cuda_runtime.h>
#include <cuda_bf16.h>

// BodyKinematics tree FK. B=4096, N=256, E=255.
// Round 17: R15 VERBATIM (PDL pack + lean fk, best: 21.1us) with exactly one
// change: ftanh's exp(2x) folded into a single ex2.approx(x*2*log2(e))
// (R16 bundled this with smem la-staging which regressed; this isolates the
// strictly-positive half).

#define NN 256
#define EE 255
#define PI_F 3.14159265358979f
#define TWO_LOG2E 2.88539008177793f   // 2 * log2(e)

__device__ float4 g_tip[3 * EE];   // [row][edge] planes, lane-coalesced reads

__global__ void pack_kernel(const float* __restrict__ tip) {
    const int j = blockIdx.x * blockDim.x + threadIdx.x;   // float4 index in (E,4,4)
    if (j < EE * 4) {
        const int e = j >> 2, row = j & 3;
        const float4 v = ((const float4*)tip)[j];
        if (row < 3) g_tip[row * EE + e] = v;
    }
    // Release the dependent fk grid as early as possible.
    cudaTriggerProgrammaticLaunchCompletion();
}

__device__ __forceinline__ float ftanh(float x) {
    float ax = fabsf(x);
    float t;
    asm("ex2.approx.f32 %0, %1;" : "=f"(t) : "f"(ax * TWO_LOG2E));  // exp(2*ax)
    float r = __fdividef(t - 1.0f, t + 1.0f);
    r = ax > 40.0f ? 1.0f : r;
    return copysignf(r, x);
}

// world_row = P.x*L0 + P.y*L1 + P.z*L2 (+ P.w in translation slot)
__device__ __forceinline__ float4 aff(float4 P, float4 L0, float4 L1, float4 L2) {
    float4 w;
    w.x = fmaf(P.x, L0.x, fmaf(P.y, L1.x, P.z * L2.x));
    w.y = fmaf(P.x, L0.y, fmaf(P.y, L1.y, P.z * L2.y));
    w.z = fmaf(P.x, L0.z, fmaf(P.y, L1.z, P.z * L2.z));
    w.w = fmaf(P.x, L0.w, fmaf(P.y, L1.w, fmaf(P.z, L2.w, P.w)));
    return w;
}

__global__ __launch_bounds__(256) void fk_kernel(
    const float* __restrict__ la,    // (B, 3E)
    float* __restrict__ out)         // (B, N, 4, 4)
{
    // FIRST: wait for pack_kernel's g_tip writes. Nothing is live here, so
    // this costs no registers — it only gates instruction issue.
    cudaGridDependencySynchronize();

    // World affines: S[node*3 + row]. Stride-3 float4 granules (48 B/node,
    // coprime with banks) -> conflict-free LDS.128/STS.128. 12 KB.
    __shared__ float4 S[NN * 3];

    const int b = blockIdx.x;
    const int t = threadIdx.x;

    float4 L0, L1, L2;   // local affine rows for node t+1 (edge t)

    if (t < EE) {
        const float* lap = la + (size_t)b * (3 * EE) + 3 * t;
        const float tha = PI_F * ftanh(lap[0]);
        const float thb = PI_F * ftanh(lap[1]);
        const float thc = PI_F * ftanh(lap[2]);

        float sa, ca, sb, cb, sc, cc;
        __sincosf(tha, &sa, &ca);
        __sincosf(thb, &sb, &cb);
        __sincosf(thc, &sc, &cc);

        // M = Rx(a) * Ry(b) * Rz(c)
        float M[9];
        M[0] = cb * cc;
        M[1] = -cb * sc;
        M[2] = sb;
        M[3] = fmaf(sa * sb, cc, ca * sc);
        M[4] = fmaf(-sa * sb, sc, ca * cc);
        M[5] = -sa * cb;
        M[6] = fmaf(-ca * sb, cc, sa * sc);
        M[7] = fmaf(ca * sb, sc, sa * cc);
        M[8] = ca * cb;

        const float4 T0 = g_tip[t];
        const float4 T1 = g_tip[EE + t];
        const float4 T2 = g_tip[2 * EE + t];
        #define MT(r, D)                                                        \
            D.x = fmaf(M[3*r], T0.x, fmaf(M[3*r+1], T1.x, M[3*r+2] * T2.x));    \
            D.y = fmaf(M[3*r], T0.y, fmaf(M[3*r+1], T1.y, M[3*r+2] * T2.y));    \
            D.z = fmaf(M[3*r], T0.z, fmaf(M[3*r+1], T1.z, M[3*r+2] * T2.z));    \
            D.w = fmaf(M[3*r], T0.w, fmaf(M[3*r+1], T1.w, M[3*r+2] * T2.w));
        MT(0, L0) MT(1, L1) MT(2, L2)
        #undef MT
    } else {
        // Root: identity world.
        S[0] = make_float4(1.f, 0.f, 0.f, 0.f);
        S[1] = make_float4(0.f, 1.f, 0.f, 0.f);
        S[2] = make_float4(0.f, 0.f, 1.f, 0.f);
    }
    __syncthreads();

    // Level-parallel tree on node n = t+1: levels lo = 1,3,7,15,31,63,127,255.
    const int n = t + 1;   // thread 255 -> n=256, never active below
    #pragma unroll
    for (int lo = 1; lo < NN; lo = 2 * lo + 1) {
        const int hi = (2 * lo + 1 < NN) ? (2 * lo + 1) : NN;
        if (n >= lo && n < hi) {
            const int p = (n - 1) >> 1;
            const float4 P0 = S[3 * p], P1 = S[3 * p + 1], P2 = S[3 * p + 2];
            S[3 * n]     = aff(P0, L0, L1, L2);
            S[3 * n + 1] = aff(P1, L0, L1, L2);
            S[3 * n + 2] = aff(P2, L0, L1, L2);
        }
        __syncthreads();
    }

    // Coalesced output: CTA writes its 16KB block in 4 contiguous rounds.
    float4* o = (float4*)(out + (size_t)b * NN * 16);
    const float4 r3 = make_float4(0.f, 0.f, 0.f, 1.f);
    #pragma unroll
    for (int k = 0; k < 4; ++k) {
        const int j = k * NN + t;
        const int node = j >> 2, row = j & 3;
        o[j] = (row < 3) ? S[3 * node + row] : r3;
    }
}

extern "C" void kernel_launch(void* const* d_in, const int* in_sizes, int n_in,
                              void* d_out, int out_size) {
    const float* la  = (const float*)d_in[0];
    const float* tip = (const float*)d_in[1];
    float* out = (float*)d_out;

    const int B = in_sizes[0] / (3 * EE);

    pack_kernel<<<4, 256>>>(tip);

    // PDL: fk's grid may begin launching while pack is still running; the
    // entry-point grid-dependency sync orders the g_tip reads.
    cudaLaunchConfig_t cfg = {};
    cfg.gridDim = dim3((unsigned)B);
    cfg.blockDim = dim3(NN);
    cfg.dynamicSmemBytes = 0;
    cfg.stream = 0;
    cudaLaunchAttribute attr[1];
    attr[0].id = cudaLaunchAttributeProgrammaticStreamSerialization;
    attr[0].val.programmaticStreamSerializationAllowed = 1;
    cfg.attrs = attr;
    cfg.numAttrs = 1;
    cudaLaunchKernelEx(&cfg, fk_kernel, la, out);
}